// round 5
// baseline (speedup 1.0000x reference)
#include <cuda_runtime.h>
#include <cstdint>

#define N_PTS  65536
#define M_G    1024
#define KSEL   10
#define TPB    256
#define SPLIT  4
#define SLICE  256          // M_G / SPLIT
#define FRZ    64           // exact-sift prefix per lane
#define CAPL   16           // per-lane B-candidate cap
#define EQCAP  8
#define NEGINF (-3.402823466e38f)

// Offset form: q(x) = d^T P' d,  d = x - mu,  P' = -0.5*log2(e) * Sigma^-1.
// weight = exp2(q). Interleaved: gaussian m = s*256+i lives at pos = 4*i + s.
__device__ float4 g_p1[M_G];   // mu0, mu1, p00, p01
__device__ float2 g_p2[M_G];   // p11, (pad)

__global__ void prep_kernel(const float* __restrict__ mus,
                            const float* __restrict__ covs) {
    int m = blockIdx.x * blockDim.x + threadIdx.x;
    if (m >= M_G) return;
    float mu0 = mus[2 * m], mu1 = mus[2 * m + 1];
    float a = covs[4 * m + 0];
    float b = covs[4 * m + 1];   // symmetric
    float c = covs[4 * m + 3];
    float det = a * c - b * b;
    const float L2E = 1.4426950408889634f;
    float sc = -0.5f * L2E / det;
    float p00 = sc * c;
    float p01 = -sc * b;
    float p11 = sc * a;
    int s = m >> 8, i = m & (SLICE - 1);
    int pos = i * SPLIT + s;
    g_p1[pos] = make_float4(mu0, mu1, p00, p01);
    g_p2[pos] = make_float2(p11, 0.f);
}

__device__ __forceinline__ float ex2_approx(float x) {
    float r;
    asm("ex2.approx.ftz.f32 %0, %1;" : "=f"(r) : "f"(x));
    return r;
}

// Depth-2 branchless sorted insert into descending top[0..9] (exact fp32).
__device__ __forceinline__ void siftf(float top[KSEL], float q) {
    float mn[KSEL - 1];
    #pragma unroll
    for (int j = 1; j < KSEL; ++j) mn[j - 1] = fminf(q, top[j - 1]);
    #pragma unroll
    for (int j = 1; j < KSEL; ++j) top[j] = fmaxf(mn[j - 1], top[j]);
    top[0] = fmaxf(top[0], q);
}

__global__ void __launch_bounds__(TPB, 4) render_kernel(
    const float2* __restrict__ x,
    const float*  __restrict__ cols,
    float*        __restrict__ out)
{
    __shared__ float4        sp1[M_G];
    __shared__ float2        sp2[M_G];
    __shared__ float         candq[TPB * CAPL];
    __shared__ unsigned char candi[TPB * CAPL];
    __shared__ unsigned char seq  [TPB * EQCAP];

    int tid = threadIdx.x;
    #pragma unroll 4
    for (int i = tid; i < M_G; i += TPB) { sp1[i] = g_p1[i]; sp2[i] = g_p2[i]; }
    __syncthreads();

    int gt_ = blockIdx.x * TPB + tid;
    int p   = gt_ >> 2;         // point
    int s   = gt_ & 3;          // slice (lanes 4k..4k+3 share a point)
    float2 xv = __ldg(&x[p]);
    float x0 = xv.x, x1 = xv.y;

    // identical expression everywhere -> bitwise-reproducible q
    auto evalq = [&](int i) -> float {
        float4 c1 = sp1[i * 4 + s];       // mu0, mu1, p00, p01
        float2 c2 = sp2[i * 4 + s];       // p11
        float d0 = x0 - c1.x;
        float d1 = x1 - c1.y;
        float t0 = fmaf(c1.w, d1, c1.z * d0);   // p00*d0 + p01*d1
        float t1 = fmaf(c2.x, d1, c1.w * d0);   // p01*d0 + p11*d1
        return fmaf(d1, t1, d0 * t0);           // d^T P' d  (log2 weight)
    };

    float top[KSEL];
    #pragma unroll
    for (int j = 0; j < KSEL; ++j) top[j] = NEGINF;

    // ---- Phase A: exact sift over first FRZ of own slice ----
    #pragma unroll 2
    for (int i = 0; i < FRZ; ++i) siftf(top, evalq(i));

    // merge the 4 lane lists -> exact top-10 of the 256 sampled
    #pragma unroll
    for (int st = 1; st <= 2; st <<= 1) {
        float cur[KSEL];
        #pragma unroll
        for (int j = 0; j < KSEL; ++j) cur[j] = top[j];
        #pragma unroll
        for (int j = 0; j < KSEL; ++j)
            siftf(top, __shfl_xor_sync(0xFFFFFFFFu, cur[j], st));
    }
    float tau = top[KSEL - 1];   // exact lower bound on the final 10th

    // ---- Phase B: guard + log (q, i) survivors ----
    int cnt = 0;
    #pragma unroll 4
    for (int i = FRZ; i < SLICE; ++i) {
        float q = evalq(i);
        if (q >= tau) {
            if (cnt < CAPL) {
                candq[tid * CAPL + cnt] = q;
                candi[tid * CAPL + cnt] = (unsigned char)i;
            }
            cnt++;
        }
    }
    bool ovf = (cnt > CAPL);

    // ---- exact 10th: lane B-list -> merge -> fold into A-list ----
    float L[KSEL];
    #pragma unroll
    for (int j = 0; j < KSEL; ++j) L[j] = NEGINF;
    if (!ovf) {
        for (int j = 0; j < cnt; ++j) siftf(L, candq[tid * CAPL + j]);
    } else {
        for (int i = FRZ; i < SLICE; ++i) siftf(L, evalq(i));  // exact fallback
    }
    #pragma unroll
    for (int st = 1; st <= 2; st <<= 1) {
        float cur[KSEL];
        #pragma unroll
        for (int j = 0; j < KSEL; ++j) cur[j] = L[j];
        #pragma unroll
        for (int j = 0; j < KSEL; ++j)
            siftf(L, __shfl_xor_sync(0xFFFFFFFFu, cur[j], st));
    }
    #pragma unroll
    for (int j = 0; j < KSEL; ++j) siftf(top, L[j]);
    float t = top[KSEL - 1];     // exact 10th-largest q of all 1024

    // ---- accumulate winners; q==t ties logged for lowest-m quota fill ----
    float r0 = 0.f, r1 = 0.f, r2 = 0.f, den = 0.f;
    int gtc = 0, eqc = 0;

    auto acc = [&](int i, float q) {
        int m = s * SLICE + i;
        float v = ex2_approx(q);
        r0 = fmaf(v, __ldg(&cols[3 * m + 0]), r0);
        r1 = fmaf(v, __ldg(&cols[3 * m + 1]), r1);
        r2 = fmaf(v, __ldg(&cols[3 * m + 2]), r2);
        den += v;
    };

    #pragma unroll 2
    for (int i = 0; i < FRZ; ++i) {           // A-range rescan
        float q = evalq(i);
        if (q > t)       { acc(i, q); gtc++; }
        else if (q == t) { if (eqc < EQCAP) seq[tid * EQCAP + eqc] = (unsigned char)i; eqc++; }
    }
    if (!ovf) {                               // B winners from the log
        for (int j = 0; j < cnt; ++j) {
            float q = candq[tid * CAPL + j];
            int   i = candi[tid * CAPL + j];
            if (q > t)       { acc(i, q); gtc++; }
            else if (q == t) { if (eqc < EQCAP) seq[tid * EQCAP + eqc] = (unsigned char)i; eqc++; }
        }
    } else {                                  // exact fallback rescan
        for (int i = FRZ; i < SLICE; ++i) {
            float q = evalq(i);
            if (q > t)       { acc(i, q); gtc++; }
            else if (q == t) { if (eqc < EQCAP) seq[tid * EQCAP + eqc] = (unsigned char)i; eqc++; }
        }
    }
    if (eqc > EQCAP) eqc = EQCAP;

    // group totals + lane-ordered (== ascending m) tie quota
    int gt_tot = gtc;
    gt_tot += __shfl_xor_sync(0xFFFFFFFFu, gt_tot, 1);
    gt_tot += __shfl_xor_sync(0xFFFFFFFFu, gt_tot, 2);
    int lane = tid & 31, base = lane & ~3;
    int e0 = __shfl_sync(0xFFFFFFFFu, eqc, base + 0);
    int e1 = __shfl_sync(0xFFFFFFFFu, eqc, base + 1);
    int e2 = __shfl_sync(0xFFFFFFFFu, eqc, base + 2);
    int prefix = (s > 0 ? e0 : 0) + (s > 1 ? e1 : 0) + (s > 2 ? e2 : 0);
    int keep_eq = KSEL - gt_tot;              // >= 1 by definition of t
    int quota = min(eqc, max(0, keep_eq - prefix));
    for (int j = 0; j < quota; ++j) acc((int)seq[tid * EQCAP + j], t);

    // group reduction
    #pragma unroll
    for (int st = 1; st <= 2; st <<= 1) {
        r0  += __shfl_xor_sync(0xFFFFFFFFu, r0,  st);
        r1  += __shfl_xor_sync(0xFFFFFFFFu, r1,  st);
        r2  += __shfl_xor_sync(0xFFFFFFFFu, r2,  st);
        den += __shfl_xor_sync(0xFFFFFFFFu, den, st);
    }

    if (s == 0) {
        float inv = 1.0f / (den + 1e-6f);
        out[3 * p + 0] = r0 * inv;
        out[3 * p + 1] = r1 * inv;
        out[3 * p + 2] = r2 * inv;
    }
}

extern "C" void kernel_launch(void* const* d_in, const int* in_sizes, int n_in,
                              void* d_out, int out_size) {
    const float* xx   = (const float*)d_in[0];   // [N, 2]
    const float* mus  = (const float*)d_in[1];   // [1, M, 2]
    const float* covs = (const float*)d_in[2];   // [1, M, 2, 2]
    const float* cols = (const float*)d_in[3];   // [1, M, 3]
    float* out = (float*)d_out;                  // [N, 3]

    prep_kernel<<<(M_G + 127) / 128, 128>>>(mus, covs);
    render_kernel<<<(N_PTS * SPLIT) / TPB, TPB>>>((const float2*)xx, cols, out);
}